// round 14
// baseline (speedup 1.0000x reference)
#include <cuda_runtime.h>
#include <cuda_fp16.h>
#include <cstdint>

// VectorQuantizer on GB300: fp16 HMMA (fp16 accumulate) screening GEMM +
// exact fp32 rescore.  z (32768 x 256) f32, codebook (8192 x 256) f32.
// Output f32: [0,8388608) z_q_st, [8388608] loss, [8388609,+32768) indices.
// R14: R9/R13 champion with a 3-stage B ring (CP_WAIT(1)) so every B chunk
// has two chunks of compute to land.  113.5KB smem keeps occupancy 2.
// All compute/epilogue/rescore math byte-identical to the champion.

#define M_ROWS   32768
#define K_CODES  8192
#define D_DIM    256
#define ZQ_ELEMS (M_ROWS * D_DIM)
#define CB_ELEMS (K_CODES * D_DIM)
#define LOSS_OFF ZQ_ELEMS
#define IDX_OFF  (ZQ_ELEMS + 1)

#define GTM 128            /* rows per CTA                  */
#define GTN 128            /* codes per subtile             */
#define NSPLIT 8           /* codebook split across CTAs    */
#define CPC (K_CODES / NSPLIT)        /* 1024 codes per CTA */
#define NSUB (CPC / GTN)              /* 8 subtiles         */
#define KCH 64             /* dims per B chunk              */
#define NCHUNK (NSUB * (D_DIM / KCH)) /* 32 B chunks        */
#define NSTAGE 3
#define CAP 512
#define MARGIN 1.2e-4f     /* ~25 sigma of fp16 screen error */
#define DESCALE (-0.000244140625f)    /* -2 * 2^-13, exact  */

typedef unsigned long long ull;
typedef unsigned int       uint;

__device__ __half g_zh[ZQ_ELEMS];
__device__ __half g_cbh[CB_ELEMS];
__device__ float  g_znorm[M_ROWS];
__device__ float  g_enorm[K_CODES];
__device__ int    g_cnt[M_ROWS];
__device__ uint   g_rowmin[M_ROWS];
__device__ ull    g_cand[(size_t)M_ROWS * CAP];
__device__ double g_loss_acc;

// ------------------------------ helpers ------------------------------------
__device__ __forceinline__ uint smem_u32(const void* p) {
    uint a;
    asm("{ .reg .u64 t; cvta.to.shared.u64 t, %1; cvt.u32.u64 %0, t; }"
        : "=r"(a) : "l"(p));
    return a;
}
#define SWZ(o) ((o) ^ (((o) >> 3) & 0x70u))   /* SW128 for 128B rows */

#define CP_ASYNC16(dst, src) \
    asm volatile("cp.async.cg.shared.global [%0], [%1], 16;" \
                 :: "r"(dst), "l"(src) : "memory")
#define CP_COMMIT() asm volatile("cp.async.commit_group;" ::: "memory")
#define CP_WAIT(n)  asm volatile("cp.async.wait_group %0;" :: "n"(n) : "memory")

#define LDSM_X4(r0, r1, r2, r3, a) \
    asm volatile("ldmatrix.sync.aligned.m8n8.x4.shared.b16 {%0,%1,%2,%3}, [%4];" \
                 : "=r"(r0), "=r"(r1), "=r"(r2), "=r"(r3) : "r"(a))

// fp16 MMA with fp16 accumulator: 2 packed b32 C/D regs.
#define MMA_F16ACC(c, a, b) \
    asm volatile("mma.sync.aligned.m16n8k16.row.col.f16.f16.f16.f16 " \
                 "{%0,%1},{%2,%3,%4,%5},{%6,%7},{%0,%1};" \
                 : "+r"((c)[0]), "+r"((c)[1]) \
                 : "r"((a)[0]), "r"((a)[1]), "r"((a)[2]), "r"((a)[3]), \
                   "r"((b)[0]), "r"((b)[1]))

__device__ __forceinline__ uint fkey(float f) {
    uint u = __float_as_uint(f);
    return (u & 0x80000000u) ? ~u : (u | 0x80000000u);
}
__device__ __forceinline__ float keyf(uint k) {
    uint u = (k & 0x80000000u) ? (k & 0x7fffffffu) : ~k;
    return __uint_as_float(u);
}

// ---------------------------------------------------------------------------
// K1: fused prep.  One warp per row (z rows then codebook rows):
//  - norm with the SAME per-lane accumulation order as all prior rounds,
//  - fp16 conversion (codebook scaled by 2^13, exact pow2 in fp32),
//  - per-row state init; warp 0 zeros the loss accumulator.
// ---------------------------------------------------------------------------
__global__ void vq_prep_kernel(const float* __restrict__ z,
                               const float* __restrict__ cb) {
    int gw   = (blockIdx.x * blockDim.x + threadIdx.x) >> 5;
    int lane = threadIdx.x & 31;
    if (gw == 0 && lane == 0) g_loss_acc = 0.0;
    if (gw >= M_ROWS + K_CODES) return;

    bool isz = (gw < M_ROWS);
    const float* src = isz ? (z + (size_t)gw * D_DIM)
                           : (cb + (size_t)(gw - M_ROWS) * D_DIM);

    // --- norm: byte-identical order to the verified norms kernel ---
    float s = 0.f;
#pragma unroll
    for (int i = 0; i < D_DIM / 32; ++i) {
        float v = src[lane + i * 32];
        s = __fmaf_rn(v, v, s);
    }
#pragma unroll
    for (int off = 16; off > 0; off >>= 1)
        s = __fadd_rn(s, __shfl_xor_sync(0xffffffffu, s, off));

    // --- fp16 conversion (vectorized; scale codebook by 2^13 exact) ---
    {
        const float4* s4 = reinterpret_cast<const float4*>(src);
        uint2* dst = isz
            ? reinterpret_cast<uint2*>(g_zh  + (size_t)gw * D_DIM)
            : reinterpret_cast<uint2*>(g_cbh + (size_t)(gw - M_ROWS) * D_DIM);
        float sc = isz ? 1.0f : 8192.0f;
#pragma unroll
        for (int q = 0; q < 2; ++q) {
            float4 v = s4[lane + q * 32];
            __half2 h0 = __floats2half2_rn(v.x * sc, v.y * sc);
            __half2 h1 = __floats2half2_rn(v.z * sc, v.w * sc);
            dst[lane + q * 32] = make_uint2(*(uint*)&h0, *(uint*)&h1);
        }
    }

    if (lane == 0) {
        if (isz) {
            g_znorm[gw]  = s;
            g_cnt[gw]    = 0;
            g_rowmin[gw] = 0xFFFFFFFFu;
        } else {
            g_enorm[gw - M_ROWS] = s;
        }
    }
}

// ---------------------------------------------------------------------------
// K2: A-resident fp16 screening GEMM.  CTA = 128 rows x 1024 codes.
// A: 4 sub-tiles of 128x64 (16KB), loaded once (group 0, with B chunk 0).
// B: 3-stage 16KB ring, CP_WAIT(1) => each chunk gets 2 compute-chunks of
// latency cover.  8 warps as 2(m) x 4(n), warp tile 64x32, fp16 accs.
// Per-subtile epilogue, no barriers (atomicMin rowmin; stale threshold
// over-collects => superset => safe).
// ---------------------------------------------------------------------------
#define ACH_BYTES (GTM * KCH * 2)   /* 16384 per A sub-tile */
#define A_BYTES   (4 * ACH_BYTES)   /* 65536 */
#define B_BYTES   (GTN * KCH * 2)   /* 16384 per stage */
#define SMEM_DYN  (1024 + A_BYTES + NSTAGE * B_BYTES)   /* 114688+1024 fits occ2 */

__device__ __forceinline__ void load_b_chunk(uint bU, int kcBase, int cidx,
                                             int tid) {
    int sub = cidx >> 2, kc = cidx & 3;
#pragma unroll
    for (int i = 0; i < 4; ++i) {           // 128 codes x 8 16B-chunks
        int id = i * 256 + tid;
        int r = id >> 3, c = id & 7;
        const __half* src =
            g_cbh + (size_t)(kcBase + sub * GTN + r) * D_DIM + kc * KCH + c * 8;
        uint off = (uint)(r * 128 + c * 16);
        CP_ASYNC16(bU + SWZ(off), src);
    }
}

__global__ __launch_bounds__(256, 2) void vq_screen_kernel() {
    extern __shared__ __align__(16) char dynsmem[];
    __shared__ uint s_rowmin[GTM];

    const int tid  = threadIdx.x;
    const int wid  = tid >> 5, lane = tid & 31;
    const int rowBase = blockIdx.x * GTM;
    const int kcBase  = blockIdx.y * CPC;
    const int warp_m  = (wid >> 2) * 64;
    const int warp_n  = (wid & 3) * 32;

    uint base  = smem_u32(dynsmem);
    uint aBase = (base + 1023u) & ~1023u;
    uint bBase = aBase + A_BYTES;

    if (tid < GTM) s_rowmin[tid] = 0xFFFFFFFFu;

    // ---- load the full A tile (4 sub-tiles of 128x64), group 0 with b0 -----
#pragma unroll
    for (int t = 0; t < 4; ++t) {
#pragma unroll
        for (int i = 0; i < 4; ++i) {
            int id = i * 256 + tid;
            int r = id >> 3, c = id & 7;
            const __half* src =
                g_zh + (size_t)(rowBase + r) * D_DIM + t * KCH + c * 8;
            uint off = (uint)(r * 128 + c * 16);
            CP_ASYNC16(aBase + t * ACH_BYTES + SWZ(off), src);
        }
    }
    load_b_chunk(bBase, kcBase, 0, tid);
    CP_COMMIT();                               // group: A + b0
    load_b_chunk(bBase + B_BYTES, kcBase, 1, tid);
    CP_COMMIT();                               // group: b1

    uint  acc[4][4][2];   // fp16x2 accumulators
    float en_r[4][2];

    for (int cidx = 0; cidx < NCHUNK; ++cidx) {
        if (cidx < NCHUNK - 1) { CP_WAIT(1); } else { CP_WAIT(0); }
        __syncthreads();          // chunk cidx (and A) resident; all warps
                                  // done reading stage (cidx+2)%3 (iter cidx-1)
        if (cidx + 2 < NCHUNK) {
            load_b_chunk(bBase + ((cidx + 2) % NSTAGE) * B_BYTES, kcBase,
                         cidx + 2, tid);
            CP_COMMIT();
        }

        if ((cidx & 3) == 0) {    // subtile start: reset acc, prefetch enorm
            int sub = cidx >> 2;
#pragma unroll
            for (int mi = 0; mi < 4; ++mi)
#pragma unroll
                for (int ni = 0; ni < 4; ++ni) {
                    acc[mi][ni][0] = 0u; acc[mi][ni][1] = 0u;
                }
#pragma unroll
            for (int ni = 0; ni < 4; ++ni)
#pragma unroll
                for (int j = 0; j < 2; ++j)
                    en_r[ni][j] = g_enorm[kcBase + sub * GTN + warp_n + ni * 8
                                          + (lane & 3) * 2 + j];
        }

        uint aT = aBase + (cidx & 3) * ACH_BYTES;
        uint bT = bBase + (cidx % NSTAGE) * B_BYTES;
#pragma unroll
        for (int ks = 0; ks < KCH / 16; ++ks) {
            uint afr[4][4];
#pragma unroll
            for (int mi = 0; mi < 4; ++mi) {
                uint off = (uint)((warp_m + mi * 16 + (lane & 15)) * 128
                                  + ks * 32 + (lane >> 4) * 16);
                LDSM_X4(afr[mi][0], afr[mi][1], afr[mi][2], afr[mi][3],
                        aT + SWZ(off));
            }
            uint bfr[4][2];
#pragma unroll
            for (int np = 0; np < 2; ++np) {
                uint off = (uint)((warp_n + np * 16 + (lane & 7)
                                   + ((lane >> 4) & 1) * 8) * 128
                                  + ks * 32 + ((lane >> 3) & 1) * 16);
                LDSM_X4(bfr[np * 2][0], bfr[np * 2][1],
                        bfr[np * 2 + 1][0], bfr[np * 2 + 1][1],
                        bT + SWZ(off));
            }
#pragma unroll
            for (int mi = 0; mi < 4; ++mi)
#pragma unroll
                for (int ni = 0; ni < 4; ++ni)
                    MMA_F16ACC(acc[mi][ni], afr[mi], bfr[ni]);
        }

        if ((cidx & 3) == 3) {    // subtile end: epilogue (no barriers)
            int sub = cidx >> 2;
#pragma unroll
            for (int mi = 0; mi < 4; ++mi) {
#pragma unroll
                for (int h = 0; h < 2; ++h) {
                    int rl = warp_m + mi * 16 + h * 8 + (lane >> 2);
                    float dloc[4][2];
                    float m = 3.4028235e38f;
#pragma unroll
                    for (int ni = 0; ni < 4; ++ni) {
                        __half2 hv = *reinterpret_cast<__half2*>(
                                         &acc[mi][ni][h]);
                        float2 f = __half22float2(hv);
                        // d = en - 2 * dot / 2^13  (DESCALE exact pow2)
                        float d0 = __fmaf_rn(DESCALE, f.x, en_r[ni][0]);
                        float d1 = __fmaf_rn(DESCALE, f.y, en_r[ni][1]);
                        dloc[ni][0] = d0; dloc[ni][1] = d1;
                        m = fminf(m, fminf(d0, d1));
                    }
                    atomicMin(&s_rowmin[rl], fkey(m));   // update FIRST
                    float thr = keyf(s_rowmin[rl]) + MARGIN;
                    int   row = rowBase + rl;
#pragma unroll
                    for (int ni = 0; ni < 4; ++ni)
#pragma unroll
                        for (int j = 0; j < 2; ++j) {
                            float d = dloc[ni][j];
                            if (d < thr) {
                                int code = kcBase + sub * GTN + warp_n + ni * 8
                                           + (lane & 3) * 2 + j;
                                int pos = atomicAdd(&g_cnt[row], 1);
                                if (pos < CAP)
                                    g_cand[(size_t)row * CAP + pos] =
                                        ((ull)__float_as_uint(d) << 32)
                                        | (uint)code;
                            }
                        }
                }
            }
        }
    }

    __syncthreads();
    if (tid < GTM)
        atomicMin(&g_rowmin[rowBase + tid], s_rowmin[tid]);
}

// ---------------------------------------------------------------------------
// K3: fused exact rescore + straight-through output + loss + index output.
// One warp per row.  Distance math byte-identical to prior rounds.
// ---------------------------------------------------------------------------
__global__ void vq_rescore_kernel(const float* __restrict__ z,
                                  const float* __restrict__ cb,
                                  float* __restrict__ out, int out_size) {
    int gw   = (blockIdx.x * blockDim.x + threadIdx.x) >> 5;
    int lane = threadIdx.x & 31;
    if (gw >= M_ROWS) return;
    int row = gw;

    float zn     = g_znorm[row];
    float thresh = keyf(g_rowmin[row]) + MARGIN;
    int   cnt    = g_cnt[row];

    const float* zr = z + (size_t)row * D_DIM;
    float bestv = 3.4028235e38f;
    int   besti = K_CODES;

    if (cnt <= CAP) {
        for (int b = 0; b < cnt; b += 32) {
            int  i = b + lane;
            int  c = 0;
            bool q = false;
            if (i < cnt) {
                ull e = g_cand[(size_t)row * CAP + i];
                q = __uint_as_float((uint)(e >> 32)) < thresh;
                c = (int)(uint)(e & 0xffffffffull);
            }
            uint bal = __ballot_sync(0xffffffffu, q);
            while (bal) {
                int src = __ffs(bal) - 1; bal &= bal - 1;
                int cc  = __shfl_sync(0xffffffffu, c, src);
                const float* er = cb + (size_t)cc * D_DIM;
                float p = 0.f;
#pragma unroll
                for (int k = 0; k < 8; ++k)
                    p = __fmaf_rn(zr[lane + 32 * k], er[lane + 32 * k], p);
#pragma unroll
                for (int off = 16; off > 0; off >>= 1)
                    p = __fadd_rn(p, __shfl_xor_sync(0xffffffffu, p, off));
                float dv = __fmaf_rn(-2.f, p, __fadd_rn(zn, g_enorm[cc]));
                if (dv < bestv || (dv == bestv && cc < besti)) {
                    bestv = dv; besti = cc;
                }
            }
        }
    } else {
        for (int cc = 0; cc < K_CODES; ++cc) {   // overflow fallback
            const float* er = cb + (size_t)cc * D_DIM;
            float p = 0.f;
#pragma unroll
            for (int k = 0; k < 8; ++k)
                p = __fmaf_rn(zr[lane + 32 * k], er[lane + 32 * k], p);
#pragma unroll
            for (int off = 16; off > 0; off >>= 1)
                p = __fadd_rn(p, __shfl_xor_sync(0xffffffffu, p, off));
            float dv = __fmaf_rn(-2.f, p, __fadd_rn(zn, g_enorm[cc]));
            if (dv < bestv) { bestv = dv; besti = cc; }
        }
    }

    // ---- fused gather / straight-through output / loss ---------------------
    int idx = besti;            // identical in every lane
    const float* er = cb + (size_t)idx * D_DIM;
    float ls = 0.f;
#pragma unroll
    for (int k = 0; k < 8; ++k) {
        float zq   = er[lane + 32 * k];
        float zv   = zr[lane + 32 * k];
        float diff = __fadd_rn(zq, -zv);                       // fl(z_q - z)
        out[(size_t)row * D_DIM + lane + 32 * k] = __fadd_rn(zv, diff);
        ls = __fmaf_rn(diff, diff, ls);
    }
#pragma unroll
    for (int off = 16; off > 0; off >>= 1)
        ls += __shfl_xor_sync(0xffffffffu, ls, off);
    if (lane == 0) {
        atomicAdd(&g_loss_acc, (double)ls);
        if (IDX_OFF + row < out_size) out[IDX_OFF + row] = (float)idx;
    }
}

// ---------------------------------------------------------------------------
// K4: loss = 1.25 * mean((z_q - z)^2)
// ---------------------------------------------------------------------------
__global__ void vq_finalize_kernel(float* __restrict__ out, int out_size) {
    if (LOSS_OFF < out_size)
        out[LOSS_OFF] = (float)(1.25 * g_loss_acc / (double)ZQ_ELEMS);
}

// ---------------------------------------------------------------------------
extern "C" void kernel_launch(void* const* d_in, const int* in_sizes, int n_in,
                              void* d_out, int out_size) {
    const float* z  = (const float*)d_in[0];
    const float* cb = (const float*)d_in[1];
    if (n_in >= 2 && in_sizes[0] == CB_ELEMS && in_sizes[1] == ZQ_ELEMS) {
        const float* tmp = z; z = cb; cb = tmp;
    }
    float* out = (float*)d_out;

    static bool attr_set = false;
    if (!attr_set) {
        cudaFuncSetAttribute(vq_screen_kernel,
                             cudaFuncAttributeMaxDynamicSharedMemorySize,
                             SMEM_DYN);
        attr_set = true;
    }

    int nwarps = M_ROWS + K_CODES;
    vq_prep_kernel<<<(nwarps * 32 + 255) / 256, 256>>>(z, cb);

    dim3 sgrid(M_ROWS / GTM, NSPLIT);
    vq_screen_kernel<<<sgrid, 256, SMEM_DYN>>>();

    vq_rescore_kernel<<<(M_ROWS * 32 + 255) / 256, 256>>>(z, cb, out, out_size);
    vq_finalize_kernel<<<1, 1>>>(out, out_size);
}

// round 15
// speedup vs baseline: 1.5969x; 1.5969x over previous
#include <cuda_runtime.h>
#include <cuda_fp16.h>
#include <cstdint>

// VectorQuantizer on GB300: fp16 HMMA (fp16 accumulate) screening GEMM +
// exact fp32 rescore.  z (32768 x 256) f32, codebook (8192 x 256) f32.
// Output f32: [0,8388608) z_q_st, [8388608] loss, [8388609,+32768) indices.
// R15 FINAL: the verified champion (R9/R13).  2-stage B ring at occupancy 2
// (3-stage dropped occ to 1 and regressed).  Screen sits at the fallback-HMMA
// issue floor; exact-fp32 rescore decides all indices (rel_err 0.0, 8 runs).

#define M_ROWS   32768
#define K_CODES  8192
#define D_DIM    256
#define ZQ_ELEMS (M_ROWS * D_DIM)
#define CB_ELEMS (K_CODES * D_DIM)
#define LOSS_OFF ZQ_ELEMS
#define IDX_OFF  (ZQ_ELEMS + 1)

#define GTM 128            /* rows per CTA                  */
#define GTN 128            /* codes per subtile             */
#define NSPLIT 8           /* codebook split across CTAs    */
#define CPC (K_CODES / NSPLIT)        /* 1024 codes per CTA */
#define NSUB (CPC / GTN)              /* 8 subtiles         */
#define KCH 64             /* dims per B chunk              */
#define NCHUNK (NSUB * (D_DIM / KCH)) /* 32 B chunks        */
#define CAP 512
#define MARGIN 1.2e-4f     /* ~25 sigma of fp16 screen error */
#define DESCALE (-0.000244140625f)    /* -2 * 2^-13, exact  */

typedef unsigned long long ull;
typedef unsigned int       uint;

__device__ __half g_zh[ZQ_ELEMS];
__device__ __half g_cbh[CB_ELEMS];
__device__ float  g_znorm[M_ROWS];
__device__ float  g_enorm[K_CODES];
__device__ int    g_cnt[M_ROWS];
__device__ uint   g_rowmin[M_ROWS];
__device__ ull    g_cand[(size_t)M_ROWS * CAP];
__device__ double g_loss_acc;

// ------------------------------ helpers ------------------------------------
__device__ __forceinline__ uint smem_u32(const void* p) {
    uint a;
    asm("{ .reg .u64 t; cvta.to.shared.u64 t, %1; cvt.u32.u64 %0, t; }"
        : "=r"(a) : "l"(p));
    return a;
}
#define SWZ(o) ((o) ^ (((o) >> 3) & 0x70u))   /* SW128 for 128B rows */

#define CP_ASYNC16(dst, src) \
    asm volatile("cp.async.cg.shared.global [%0], [%1], 16;" \
                 :: "r"(dst), "l"(src) : "memory")
#define CP_COMMIT() asm volatile("cp.async.commit_group;" ::: "memory")
#define CP_WAIT(n)  asm volatile("cp.async.wait_group %0;" :: "n"(n) : "memory")

#define LDSM_X4(r0, r1, r2, r3, a) \
    asm volatile("ldmatrix.sync.aligned.m8n8.x4.shared.b16 {%0,%1,%2,%3}, [%4];" \
                 : "=r"(r0), "=r"(r1), "=r"(r2), "=r"(r3) : "r"(a))

// fp16 MMA with fp16 accumulator: 2 packed b32 C/D regs.
#define MMA_F16ACC(c, a, b) \
    asm volatile("mma.sync.aligned.m16n8k16.row.col.f16.f16.f16.f16 " \
                 "{%0,%1},{%2,%3,%4,%5},{%6,%7},{%0,%1};" \
                 : "+r"((c)[0]), "+r"((c)[1]) \
                 : "r"((a)[0]), "r"((a)[1]), "r"((a)[2]), "r"((a)[3]), \
                   "r"((b)[0]), "r"((b)[1]))

__device__ __forceinline__ uint fkey(float f) {
    uint u = __float_as_uint(f);
    return (u & 0x80000000u) ? ~u : (u | 0x80000000u);
}
__device__ __forceinline__ float keyf(uint k) {
    uint u = (k & 0x80000000u) ? (k & 0x7fffffffu) : ~k;
    return __uint_as_float(u);
}

// ---------------------------------------------------------------------------
// K1: fused prep.  One warp per row (z rows then codebook rows):
//  - norm with the SAME per-lane accumulation order as all prior rounds,
//  - fp16 conversion (codebook scaled by 2^13, exact pow2 in fp32),
//  - per-row state init; warp 0 zeros the loss accumulator.
// ---------------------------------------------------------------------------
__global__ void vq_prep_kernel(const float* __restrict__ z,
                               const float* __restrict__ cb) {
    int gw   = (blockIdx.x * blockDim.x + threadIdx.x) >> 5;
    int lane = threadIdx.x & 31;
    if (gw == 0 && lane == 0) g_loss_acc = 0.0;
    if (gw >= M_ROWS + K_CODES) return;

    bool isz = (gw < M_ROWS);
    const float* src = isz ? (z + (size_t)gw * D_DIM)
                           : (cb + (size_t)(gw - M_ROWS) * D_DIM);

    // --- norm: byte-identical order to the verified norms kernel ---
    float s = 0.f;
#pragma unroll
    for (int i = 0; i < D_DIM / 32; ++i) {
        float v = src[lane + i * 32];
        s = __fmaf_rn(v, v, s);
    }
#pragma unroll
    for (int off = 16; off > 0; off >>= 1)
        s = __fadd_rn(s, __shfl_xor_sync(0xffffffffu, s, off));

    // --- fp16 conversion (vectorized; scale codebook by 2^13 exact) ---
    {
        const float4* s4 = reinterpret_cast<const float4*>(src);
        uint2* dst = isz
            ? reinterpret_cast<uint2*>(g_zh  + (size_t)gw * D_DIM)
            : reinterpret_cast<uint2*>(g_cbh + (size_t)(gw - M_ROWS) * D_DIM);
        float sc = isz ? 1.0f : 8192.0f;
#pragma unroll
        for (int q = 0; q < 2; ++q) {
            float4 v = s4[lane + q * 32];
            __half2 h0 = __floats2half2_rn(v.x * sc, v.y * sc);
            __half2 h1 = __floats2half2_rn(v.z * sc, v.w * sc);
            dst[lane + q * 32] = make_uint2(*(uint*)&h0, *(uint*)&h1);
        }
    }

    if (lane == 0) {
        if (isz) {
            g_znorm[gw]  = s;
            g_cnt[gw]    = 0;
            g_rowmin[gw] = 0xFFFFFFFFu;
        } else {
            g_enorm[gw - M_ROWS] = s;
        }
    }
}

// ---------------------------------------------------------------------------
// K2: A-resident fp16 screening GEMM.  CTA = 128 rows x 1024 codes.
// A: 4 sub-tiles of 128x64 (16KB), loaded once.  B: 2-stage 16KB ring,
// one barrier per chunk.  8 warps as 2(m) x 4(n), warp tile 64x32.
// fp16 accumulators (2 packed regs per 16x8 frag).  Per-subtile epilogue,
// no barriers (atomicMin rowmin; stale threshold over-collects => safe).
// ---------------------------------------------------------------------------
#define ACH_BYTES (GTM * KCH * 2)   /* 16384 per A sub-tile */
#define A_BYTES   (4 * ACH_BYTES)   /* 65536 */
#define B_BYTES   (GTN * KCH * 2)   /* 16384 per stage */
#define SMEM_DYN  (1024 + A_BYTES + 2 * B_BYTES)   /* 99328 -> occupancy 2 */

__device__ __forceinline__ void load_b_chunk(uint bU, int kcBase, int cidx,
                                             int tid) {
    int sub = cidx >> 2, kc = cidx & 3;
#pragma unroll
    for (int i = 0; i < 4; ++i) {           // 128 codes x 8 16B-chunks
        int id = i * 256 + tid;
        int r = id >> 3, c = id & 7;
        const __half* src =
            g_cbh + (size_t)(kcBase + sub * GTN + r) * D_DIM + kc * KCH + c * 8;
        uint off = (uint)(r * 128 + c * 16);
        CP_ASYNC16(bU + SWZ(off), src);
    }
}

__global__ __launch_bounds__(256, 2) void vq_screen_kernel() {
    extern __shared__ __align__(16) char dynsmem[];
    __shared__ uint s_rowmin[GTM];

    const int tid  = threadIdx.x;
    const int wid  = tid >> 5, lane = tid & 31;
    const int rowBase = blockIdx.x * GTM;
    const int kcBase  = blockIdx.y * CPC;
    const int warp_m  = (wid >> 2) * 64;
    const int warp_n  = (wid & 3) * 32;

    uint base  = smem_u32(dynsmem);
    uint aBase = (base + 1023u) & ~1023u;
    uint bBase = aBase + A_BYTES;

    if (tid < GTM) s_rowmin[tid] = 0xFFFFFFFFu;

    // ---- load the full A tile (4 sub-tiles of 128x64) ----------------------
#pragma unroll
    for (int t = 0; t < 4; ++t) {
#pragma unroll
        for (int i = 0; i < 4; ++i) {
            int id = i * 256 + tid;
            int r = id >> 3, c = id & 7;
            const __half* src =
                g_zh + (size_t)(rowBase + r) * D_DIM + t * KCH + c * 8;
            uint off = (uint)(r * 128 + c * 16);
            CP_ASYNC16(aBase + t * ACH_BYTES + SWZ(off), src);
        }
    }
    load_b_chunk(bBase, kcBase, 0, tid);
    CP_COMMIT();

    uint  acc[4][4][2];   // fp16x2 accumulators
    float en_r[4][2];

    for (int cidx = 0; cidx < NCHUNK; ++cidx) {
        CP_WAIT(0);
        __syncthreads();          // chunk cidx visible; all warps done with
                                  // stage (cidx+1)&1 (read in iter cidx-1)
        if (cidx + 1 < NCHUNK) {
            load_b_chunk(bBase + ((cidx + 1) & 1) * B_BYTES, kcBase,
                         cidx + 1, tid);
            CP_COMMIT();
        }

        if ((cidx & 3) == 0) {    // subtile start: reset acc, prefetch enorm
            int sub = cidx >> 2;
#pragma unroll
            for (int mi = 0; mi < 4; ++mi)
#pragma unroll
                for (int ni = 0; ni < 4; ++ni) {
                    acc[mi][ni][0] = 0u; acc[mi][ni][1] = 0u;
                }
#pragma unroll
            for (int ni = 0; ni < 4; ++ni)
#pragma unroll
                for (int j = 0; j < 2; ++j)
                    en_r[ni][j] = g_enorm[kcBase + sub * GTN + warp_n + ni * 8
                                          + (lane & 3) * 2 + j];
        }

        uint aT = aBase + (cidx & 3) * ACH_BYTES;
        uint bT = bBase + (cidx & 1) * B_BYTES;
#pragma unroll
        for (int ks = 0; ks < KCH / 16; ++ks) {
            uint afr[4][4];
#pragma unroll
            for (int mi = 0; mi < 4; ++mi) {
                uint off = (uint)((warp_m + mi * 16 + (lane & 15)) * 128
                                  + ks * 32 + (lane >> 4) * 16);
                LDSM_X4(afr[mi][0], afr[mi][1], afr[mi][2], afr[mi][3],
                        aT + SWZ(off));
            }
            uint bfr[4][2];
#pragma unroll
            for (int np = 0; np < 2; ++np) {
                uint off = (uint)((warp_n + np * 16 + (lane & 7)
                                   + ((lane >> 4) & 1) * 8) * 128
                                  + ks * 32 + ((lane >> 3) & 1) * 16);
                LDSM_X4(bfr[np * 2][0], bfr[np * 2][1],
                        bfr[np * 2 + 1][0], bfr[np * 2 + 1][1],
                        bT + SWZ(off));
            }
#pragma unroll
            for (int mi = 0; mi < 4; ++mi)
#pragma unroll
                for (int ni = 0; ni < 4; ++ni)
                    MMA_F16ACC(acc[mi][ni], afr[mi], bfr[ni]);
        }

        if ((cidx & 3) == 3) {    // subtile end: epilogue (no barriers)
            int sub = cidx >> 2;
#pragma unroll
            for (int mi = 0; mi < 4; ++mi) {
#pragma unroll
                for (int h = 0; h < 2; ++h) {
                    int rl = warp_m + mi * 16 + h * 8 + (lane >> 2);
                    float dloc[4][2];
                    float m = 3.4028235e38f;
#pragma unroll
                    for (int ni = 0; ni < 4; ++ni) {
                        __half2 hv = *reinterpret_cast<__half2*>(
                                         &acc[mi][ni][h]);
                        float2 f = __half22float2(hv);
                        // d = en - 2 * dot / 2^13  (DESCALE exact pow2)
                        float d0 = __fmaf_rn(DESCALE, f.x, en_r[ni][0]);
                        float d1 = __fmaf_rn(DESCALE, f.y, en_r[ni][1]);
                        dloc[ni][0] = d0; dloc[ni][1] = d1;
                        m = fminf(m, fminf(d0, d1));
                    }
                    atomicMin(&s_rowmin[rl], fkey(m));   // update FIRST
                    float thr = keyf(s_rowmin[rl]) + MARGIN;
                    int   row = rowBase + rl;
#pragma unroll
                    for (int ni = 0; ni < 4; ++ni)
#pragma unroll
                        for (int j = 0; j < 2; ++j) {
                            float d = dloc[ni][j];
                            if (d < thr) {
                                int code = kcBase + sub * GTN + warp_n + ni * 8
                                           + (lane & 3) * 2 + j;
                                int pos = atomicAdd(&g_cnt[row], 1);
                                if (pos < CAP)
                                    g_cand[(size_t)row * CAP + pos] =
                                        ((ull)__float_as_uint(d) << 32)
                                        | (uint)code;
                            }
                        }
                }
            }
        }
    }

    __syncthreads();
    if (tid < GTM)
        atomicMin(&g_rowmin[rowBase + tid], s_rowmin[tid]);
}

// ---------------------------------------------------------------------------
// K3: fused exact rescore + straight-through output + loss + index output.
// One warp per row.  Distance math byte-identical to prior rounds.
// ---------------------------------------------------------------------------
__global__ void vq_rescore_kernel(const float* __restrict__ z,
                                  const float* __restrict__ cb,
                                  float* __restrict__ out, int out_size) {
    int gw   = (blockIdx.x * blockDim.x + threadIdx.x) >> 5;
    int lane = threadIdx.x & 31;
    if (gw >= M_ROWS) return;
    int row = gw;

    float zn     = g_znorm[row];
    float thresh = keyf(g_rowmin[row]) + MARGIN;
    int   cnt    = g_cnt[row];

    const float* zr = z + (size_t)row * D_DIM;
    float bestv = 3.4028235e38f;
    int   besti = K_CODES;

    if (cnt <= CAP) {
        for (int b = 0; b < cnt; b += 32) {
            int  i = b + lane;
            int  c = 0;
            bool q = false;
            if (i < cnt) {
                ull e = g_cand[(size_t)row * CAP + i];
                q = __uint_as_float((uint)(e >> 32)) < thresh;
                c = (int)(uint)(e & 0xffffffffull);
            }
            uint bal = __ballot_sync(0xffffffffu, q);
            while (bal) {
                int src = __ffs(bal) - 1; bal &= bal - 1;
                int cc  = __shfl_sync(0xffffffffu, c, src);
                const float* er = cb + (size_t)cc * D_DIM;
                float p = 0.f;
#pragma unroll
                for (int k = 0; k < 8; ++k)
                    p = __fmaf_rn(zr[lane + 32 * k], er[lane + 32 * k], p);
#pragma unroll
                for (int off = 16; off > 0; off >>= 1)
                    p = __fadd_rn(p, __shfl_xor_sync(0xffffffffu, p, off));
                float dv = __fmaf_rn(-2.f, p, __fadd_rn(zn, g_enorm[cc]));
                if (dv < bestv || (dv == bestv && cc < besti)) {
                    bestv = dv; besti = cc;
                }
            }
        }
    } else {
        for (int cc = 0; cc < K_CODES; ++cc) {   // overflow fallback
            const float* er = cb + (size_t)cc * D_DIM;
            float p = 0.f;
#pragma unroll
            for (int k = 0; k < 8; ++k)
                p = __fmaf_rn(zr[lane + 32 * k], er[lane + 32 * k], p);
#pragma unroll
            for (int off = 16; off > 0; off >>= 1)
                p = __fadd_rn(p, __shfl_xor_sync(0xffffffffu, p, off));
            float dv = __fmaf_rn(-2.f, p, __fadd_rn(zn, g_enorm[cc]));
            if (dv < bestv) { bestv = dv; besti = cc; }
        }
    }

    // ---- fused gather / straight-through output / loss ---------------------
    int idx = besti;            // identical in every lane
    const float* er = cb + (size_t)idx * D_DIM;
    float ls = 0.f;
#pragma unroll
    for (int k = 0; k < 8; ++k) {
        float zq   = er[lane + 32 * k];
        float zv   = zr[lane + 32 * k];
        float diff = __fadd_rn(zq, -zv);                       // fl(z_q - z)
        out[(size_t)row * D_DIM + lane + 32 * k] = __fadd_rn(zv, diff);
        ls = __fmaf_rn(diff, diff, ls);
    }
#pragma unroll
    for (int off = 16; off > 0; off >>= 1)
        ls += __shfl_xor_sync(0xffffffffu, ls, off);
    if (lane == 0) {
        atomicAdd(&g_loss_acc, (double)ls);
        if (IDX_OFF + row < out_size) out[IDX_OFF + row] = (float)idx;
    }
}

// ---------------------------------------------------------------------------
// K4: loss = 1.25 * mean((z_q - z)^2)
// ---------------------------------------------------------------------------
__global__ void vq_finalize_kernel(float* __restrict__ out, int out_size) {
    if (LOSS_OFF < out_size)
        out[LOSS_OFF] = (float)(1.25 * g_loss_acc / (double)ZQ_ELEMS);
}

// ---------------------------------------------------------------------------
extern "C" void kernel_launch(void* const* d_in, const int* in_sizes, int n_in,
                              void* d_out, int out_size) {
    const float* z  = (const float*)d_in[0];
    const float* cb = (const float*)d_in[1];
    if (n_in >= 2 && in_sizes[0] == CB_ELEMS && in_sizes[1] == ZQ_ELEMS) {
        const float* tmp = z; z = cb; cb = tmp;
    }
    float* out = (float*)d_out;

    static bool attr_set = false;
    if (!attr_set) {
        cudaFuncSetAttribute(vq_screen_kernel,
                             cudaFuncAttributeMaxDynamicSharedMemorySize,
                             SMEM_DYN);
        attr_set = true;
    }

    int nwarps = M_ROWS + K_CODES;
    vq_prep_kernel<<<(nwarps * 32 + 255) / 256, 256>>>(z, cb);

    dim3 sgrid(M_ROWS / GTM, NSPLIT);
    vq_screen_kernel<<<sgrid, 256, SMEM_DYN>>>();

    vq_rescore_kernel<<<(M_ROWS * 32 + 255) / 256, 256>>>(z, cb, out, out_size);
    vq_finalize_kernel<<<1, 1>>>(out, out_size);
}

// round 16
// speedup vs baseline: 1.6289x; 1.0201x over previous
#include <cuda_runtime.h>
#include <cuda_fp16.h>
#include <cstdint>

// VectorQuantizer on GB300: fp16 HMMA (fp16 accumulate) screening GEMM +
// exact fp32 rescore.  z (32768 x 256) f32, codebook (8192 x 256) f32.
// Output f32: [0,8388608) z_q_st, [8388608] loss, [8388609,+32768) indices.
// R16: champion core with GTM=64 (A tile 32KB) -> smem 66.8KB -> occupancy 3.
// Tests whether the ~9% screen overhead above the HMMA issue floor is
// latency exposure (occ3 hides it) vs bandwidth (doubled B traffic hurts).
// All epilogue/margin/rescore math byte-identical to the champion.

#define M_ROWS   32768
#define K_CODES  8192
#define D_DIM    256
#define ZQ_ELEMS (M_ROWS * D_DIM)
#define CB_ELEMS (K_CODES * D_DIM)
#define LOSS_OFF ZQ_ELEMS
#define IDX_OFF  (ZQ_ELEMS + 1)

#define GTM 64             /* rows per CTA (was 128)        */
#define GTN 128            /* codes per subtile             */
#define NSPLIT 8           /* codebook split across CTAs    */
#define CPC (K_CODES / NSPLIT)        /* 1024 codes per CTA */
#define NSUB (CPC / GTN)              /* 8 subtiles         */
#define KCH 64             /* dims per B chunk              */
#define NCHUNK (NSUB * (D_DIM / KCH)) /* 32 B chunks        */
#define CAP 512
#define MARGIN 1.2e-4f     /* ~25 sigma of fp16 screen error */
#define DESCALE (-0.000244140625f)    /* -2 * 2^-13, exact  */

typedef unsigned long long ull;
typedef unsigned int       uint;

__device__ __half g_zh[ZQ_ELEMS];
__device__ __half g_cbh[CB_ELEMS];
__device__ float  g_znorm[M_ROWS];
__device__ float  g_enorm[K_CODES];
__device__ int    g_cnt[M_ROWS];
__device__ uint   g_rowmin[M_ROWS];
__device__ ull    g_cand[(size_t)M_ROWS * CAP];
__device__ double g_loss_acc;

// ------------------------------ helpers ------------------------------------
__device__ __forceinline__ uint smem_u32(const void* p) {
    uint a;
    asm("{ .reg .u64 t; cvta.to.shared.u64 t, %1; cvt.u32.u64 %0, t; }"
        : "=r"(a) : "l"(p));
    return a;
}
#define SWZ(o) ((o) ^ (((o) >> 3) & 0x70u))   /* SW128 for 128B rows */

#define CP_ASYNC16(dst, src) \
    asm volatile("cp.async.cg.shared.global [%0], [%1], 16;" \
                 :: "r"(dst), "l"(src) : "memory")
#define CP_COMMIT() asm volatile("cp.async.commit_group;" ::: "memory")
#define CP_WAIT(n)  asm volatile("cp.async.wait_group %0;" :: "n"(n) : "memory")

#define LDSM_X4(r0, r1, r2, r3, a) \
    asm volatile("ldmatrix.sync.aligned.m8n8.x4.shared.b16 {%0,%1,%2,%3}, [%4];" \
                 : "=r"(r0), "=r"(r1), "=r"(r2), "=r"(r3) : "r"(a))

// fp16 MMA with fp16 accumulator: 2 packed b32 C/D regs.
#define MMA_F16ACC(c, a, b) \
    asm volatile("mma.sync.aligned.m16n8k16.row.col.f16.f16.f16.f16 " \
                 "{%0,%1},{%2,%3,%4,%5},{%6,%7},{%0,%1};" \
                 : "+r"((c)[0]), "+r"((c)[1]) \
                 : "r"((a)[0]), "r"((a)[1]), "r"((a)[2]), "r"((a)[3]), \
                   "r"((b)[0]), "r"((b)[1]))

__device__ __forceinline__ uint fkey(float f) {
    uint u = __float_as_uint(f);
    return (u & 0x80000000u) ? ~u : (u | 0x80000000u);
}
__device__ __forceinline__ float keyf(uint k) {
    uint u = (k & 0x80000000u) ? (k & 0x7fffffffu) : ~k;
    return __uint_as_float(u);
}

// ---------------------------------------------------------------------------
// K1: fused prep.  One warp per row (z rows then codebook rows):
//  - norm with the SAME per-lane accumulation order as all prior rounds,
//  - fp16 conversion (codebook scaled by 2^13, exact pow2 in fp32),
//  - per-row state init; warp 0 zeros the loss accumulator.
// ---------------------------------------------------------------------------
__global__ void vq_prep_kernel(const float* __restrict__ z,
                               const float* __restrict__ cb) {
    int gw   = (blockIdx.x * blockDim.x + threadIdx.x) >> 5;
    int lane = threadIdx.x & 31;
    if (gw == 0 && lane == 0) g_loss_acc = 0.0;
    if (gw >= M_ROWS + K_CODES) return;

    bool isz = (gw < M_ROWS);
    const float* src = isz ? (z + (size_t)gw * D_DIM)
                           : (cb + (size_t)(gw - M_ROWS) * D_DIM);

    // --- norm: byte-identical order to the verified norms kernel ---
    float s = 0.f;
#pragma unroll
    for (int i = 0; i < D_DIM / 32; ++i) {
        float v = src[lane + i * 32];
        s = __fmaf_rn(v, v, s);
    }
#pragma unroll
    for (int off = 16; off > 0; off >>= 1)
        s = __fadd_rn(s, __shfl_xor_sync(0xffffffffu, s, off));

    // --- fp16 conversion (vectorized; scale codebook by 2^13 exact) ---
    {
        const float4* s4 = reinterpret_cast<const float4*>(src);
        uint2* dst = isz
            ? reinterpret_cast<uint2*>(g_zh  + (size_t)gw * D_DIM)
            : reinterpret_cast<uint2*>(g_cbh + (size_t)(gw - M_ROWS) * D_DIM);
        float sc = isz ? 1.0f : 8192.0f;
#pragma unroll
        for (int q = 0; q < 2; ++q) {
            float4 v = s4[lane + q * 32];
            __half2 h0 = __floats2half2_rn(v.x * sc, v.y * sc);
            __half2 h1 = __floats2half2_rn(v.z * sc, v.w * sc);
            dst[lane + q * 32] = make_uint2(*(uint*)&h0, *(uint*)&h1);
        }
    }

    if (lane == 0) {
        if (isz) {
            g_znorm[gw]  = s;
            g_cnt[gw]    = 0;
            g_rowmin[gw] = 0xFFFFFFFFu;
        } else {
            g_enorm[gw - M_ROWS] = s;
        }
    }
}

// ---------------------------------------------------------------------------
// K2: A-resident fp16 screening GEMM.  CTA = 64 rows x 1024 codes.
// A: 4 sub-tiles of 64x64 (8KB), loaded once (32KB total).  B: 2-stage 16KB
// ring, one barrier per chunk.  8 warps as 2(m) x 4(n), warp tile 32x32
// (mi=2).  fp16 accumulators.  Per-subtile epilogue, no barriers
// (atomicMin rowmin; stale threshold over-collects => superset => safe).
// smem ~66.8KB -> 3 CTAs/SM.
// ---------------------------------------------------------------------------
#define ACH_BYTES (GTM * KCH * 2)   /*  8192 per A sub-tile */
#define A_BYTES   (4 * ACH_BYTES)   /* 32768 */
#define B_BYTES   (GTN * KCH * 2)   /* 16384 per stage */
#define SMEM_DYN  (1024 + A_BYTES + 2 * B_BYTES)   /* 66560 -> occupancy 3 */

__device__ __forceinline__ void load_b_chunk(uint bU, int kcBase, int cidx,
                                             int tid) {
    int sub = cidx >> 2, kc = cidx & 3;
#pragma unroll
    for (int i = 0; i < 4; ++i) {           // 128 codes x 8 16B-chunks
        int id = i * 256 + tid;
        int r = id >> 3, c = id & 7;
        const __half* src =
            g_cbh + (size_t)(kcBase + sub * GTN + r) * D_DIM + kc * KCH + c * 8;
        uint off = (uint)(r * 128 + c * 16);
        CP_ASYNC16(bU + SWZ(off), src);
    }
}

__global__ __launch_bounds__(256, 3) void vq_screen_kernel() {
    extern __shared__ __align__(16) char dynsmem[];
    __shared__ uint s_rowmin[GTM];

    const int tid  = threadIdx.x;
    const int wid  = tid >> 5, lane = tid & 31;
    const int rowBase = blockIdx.x * GTM;
    const int kcBase  = blockIdx.y * CPC;
    const int warp_m  = (wid >> 2) * 32;     /* 32-row m-tile per warp */
    const int warp_n  = (wid & 3) * 32;

    uint base  = smem_u32(dynsmem);
    uint aBase = (base + 1023u) & ~1023u;
    uint bBase = aBase + A_BYTES;

    if (tid < GTM) s_rowmin[tid] = 0xFFFFFFFFu;

    // ---- load the full A tile (4 sub-tiles of 64x64) -----------------------
#pragma unroll
    for (int t = 0; t < 4; ++t) {
#pragma unroll
        for (int i = 0; i < 2; ++i) {       // 64 rows x 8 16B-chunks = 512
            int id = i * 256 + tid;
            int r = id >> 3, c = id & 7;
            const __half* src =
                g_zh + (size_t)(rowBase + r) * D_DIM + t * KCH + c * 8;
            uint off = (uint)(r * 128 + c * 16);
            CP_ASYNC16(aBase + t * ACH_BYTES + SWZ(off), src);
        }
    }
    load_b_chunk(bBase, kcBase, 0, tid);
    CP_COMMIT();

    uint  acc[2][4][2];   // fp16x2 accumulators (mi=2)
    float en_r[4][2];

    for (int cidx = 0; cidx < NCHUNK; ++cidx) {
        CP_WAIT(0);
        __syncthreads();          // chunk cidx visible; all warps done with
                                  // stage (cidx+1)&1 (read in iter cidx-1)
        if (cidx + 1 < NCHUNK) {
            load_b_chunk(bBase + ((cidx + 1) & 1) * B_BYTES, kcBase,
                         cidx + 1, tid);
            CP_COMMIT();
        }

        if ((cidx & 3) == 0) {    // subtile start: reset acc, prefetch enorm
            int sub = cidx >> 2;
#pragma unroll
            for (int mi = 0; mi < 2; ++mi)
#pragma unroll
                for (int ni = 0; ni < 4; ++ni) {
                    acc[mi][ni][0] = 0u; acc[mi][ni][1] = 0u;
                }
#pragma unroll
            for (int ni = 0; ni < 4; ++ni)
#pragma unroll
                for (int j = 0; j < 2; ++j)
                    en_r[ni][j] = g_enorm[kcBase + sub * GTN + warp_n + ni * 8
                                          + (lane & 3) * 2 + j];
        }

        uint aT = aBase + (cidx & 3) * ACH_BYTES;
        uint bT = bBase + (cidx & 1) * B_BYTES;
#pragma unroll
        for (int ks = 0; ks < KCH / 16; ++ks) {
            uint afr[2][4];
#pragma unroll
            for (int mi = 0; mi < 2; ++mi) {
                uint off = (uint)((warp_m + mi * 16 + (lane & 15)) * 128
                                  + ks * 32 + (lane >> 4) * 16);
                LDSM_X4(afr[mi][0], afr[mi][1], afr[mi][2], afr[mi][3],
                        aT + SWZ(off));
            }
            uint bfr[4][2];
#pragma unroll
            for (int np = 0; np < 2; ++np) {
                uint off = (uint)((warp_n + np * 16 + (lane & 7)
                                   + ((lane >> 4) & 1) * 8) * 128
                                  + ks * 32 + ((lane >> 3) & 1) * 16);
                LDSM_X4(bfr[np * 2][0], bfr[np * 2][1],
                        bfr[np * 2 + 1][0], bfr[np * 2 + 1][1],
                        bT + SWZ(off));
            }
#pragma unroll
            for (int mi = 0; mi < 2; ++mi)
#pragma unroll
                for (int ni = 0; ni < 4; ++ni)
                    MMA_F16ACC(acc[mi][ni], afr[mi], bfr[ni]);
        }

        if ((cidx & 3) == 3) {    // subtile end: epilogue (no barriers)
            int sub = cidx >> 2;
#pragma unroll
            for (int mi = 0; mi < 2; ++mi) {
#pragma unroll
                for (int h = 0; h < 2; ++h) {
                    int rl = warp_m + mi * 16 + h * 8 + (lane >> 2);
                    float dloc[4][2];
                    float m = 3.4028235e38f;
#pragma unroll
                    for (int ni = 0; ni < 4; ++ni) {
                        __half2 hv = *reinterpret_cast<__half2*>(
                                         &acc[mi][ni][h]);
                        float2 f = __half22float2(hv);
                        // d = en - 2 * dot / 2^13  (DESCALE exact pow2)
                        float d0 = __fmaf_rn(DESCALE, f.x, en_r[ni][0]);
                        float d1 = __fmaf_rn(DESCALE, f.y, en_r[ni][1]);
                        dloc[ni][0] = d0; dloc[ni][1] = d1;
                        m = fminf(m, fminf(d0, d1));
                    }
                    atomicMin(&s_rowmin[rl], fkey(m));   // update FIRST
                    float thr = keyf(s_rowmin[rl]) + MARGIN;
                    int   row = rowBase + rl;
#pragma unroll
                    for (int ni = 0; ni < 4; ++ni)
#pragma unroll
                        for (int j = 0; j < 2; ++j) {
                            float d = dloc[ni][j];
                            if (d < thr) {
                                int code = kcBase + sub * GTN + warp_n + ni * 8
                                           + (lane & 3) * 2 + j;
                                int pos = atomicAdd(&g_cnt[row], 1);
                                if (pos < CAP)
                                    g_cand[(size_t)row * CAP + pos] =
                                        ((ull)__float_as_uint(d) << 32)
                                        | (uint)code;
                            }
                        }
                }
            }
        }
    }

    __syncthreads();
    if (tid < GTM)
        atomicMin(&g_rowmin[rowBase + tid], s_rowmin[tid]);
}

// ---------------------------------------------------------------------------
// K3: fused exact rescore + straight-through output + loss + index output.
// One warp per row.  Distance math byte-identical to prior rounds.
// ---------------------------------------------------------------------------
__global__ void vq_rescore_kernel(const float* __restrict__ z,
                                  const float* __restrict__ cb,
                                  float* __restrict__ out, int out_size) {
    int gw   = (blockIdx.x * blockDim.x + threadIdx.x) >> 5;
    int lane = threadIdx.x & 31;
    if (gw >= M_ROWS) return;
    int row = gw;

    float zn     = g_znorm[row];
    float thresh = keyf(g_rowmin[row]) + MARGIN;
    int   cnt    = g_cnt[row];

    const float* zr = z + (size_t)row * D_DIM;
    float bestv = 3.4028235e38f;
    int   besti = K_CODES;

    if (cnt <= CAP) {
        for (int b = 0; b < cnt; b += 32) {
            int  i = b + lane;
            int  c = 0;
            bool q = false;
            if (i < cnt) {
                ull e = g_cand[(size_t)row * CAP + i];
                q = __uint_as_float((uint)(e >> 32)) < thresh;
                c = (int)(uint)(e & 0xffffffffull);
            }
            uint bal = __ballot_sync(0xffffffffu, q);
            while (bal) {
                int src = __ffs(bal) - 1; bal &= bal - 1;
                int cc  = __shfl_sync(0xffffffffu, c, src);
                const float* er = cb + (size_t)cc * D_DIM;
                float p = 0.f;
#pragma unroll
                for (int k = 0; k < 8; ++k)
                    p = __fmaf_rn(zr[lane + 32 * k], er[lane + 32 * k], p);
#pragma unroll
                for (int off = 16; off > 0; off >>= 1)
                    p = __fadd_rn(p, __shfl_xor_sync(0xffffffffu, p, off));
                float dv = __fmaf_rn(-2.f, p, __fadd_rn(zn, g_enorm[cc]));
                if (dv < bestv || (dv == bestv && cc < besti)) {
                    bestv = dv; besti = cc;
                }
            }
        }
    } else {
        for (int cc = 0; cc < K_CODES; ++cc) {   // overflow fallback
            const float* er = cb + (size_t)cc * D_DIM;
            float p = 0.f;
#pragma unroll
            for (int k = 0; k < 8; ++k)
                p = __fmaf_rn(zr[lane + 32 * k], er[lane + 32 * k], p);
#pragma unroll
            for (int off = 16; off > 0; off >>= 1)
                p = __fadd_rn(p, __shfl_xor_sync(0xffffffffu, p, off));
            float dv = __fmaf_rn(-2.f, p, __fadd_rn(zn, g_enorm[cc]));
            if (dv < bestv) { bestv = dv; besti = cc; }
        }
    }

    // ---- fused gather / straight-through output / loss ---------------------
    int idx = besti;            // identical in every lane
    const float* er = cb + (size_t)idx * D_DIM;
    float ls = 0.f;
#pragma unroll
    for (int k = 0; k < 8; ++k) {
        float zq   = er[lane + 32 * k];
        float zv   = zr[lane + 32 * k];
        float diff = __fadd_rn(zq, -zv);                       // fl(z_q - z)
        out[(size_t)row * D_DIM + lane + 32 * k] = __fadd_rn(zv, diff);
        ls = __fmaf_rn(diff, diff, ls);
    }
#pragma unroll
    for (int off = 16; off > 0; off >>= 1)
        ls += __shfl_xor_sync(0xffffffffu, ls, off);
    if (lane == 0) {
        atomicAdd(&g_loss_acc, (double)ls);
        if (IDX_OFF + row < out_size) out[IDX_OFF + row] = (float)idx;
    }
}

// ---------------------------------------------------------------------------
// K4: loss = 1.25 * mean((z_q - z)^2)
// ---------------------------------------------------------------------------
__global__ void vq_finalize_kernel(float* __restrict__ out, int out_size) {
    if (LOSS_OFF < out_size)
        out[LOSS_OFF] = (float)(1.25 * g_loss_acc / (double)ZQ_ELEMS);
}

// ---------------------------------------------------------------------------
extern "C" void kernel_launch(void* const* d_in, const int* in_sizes, int n_in,
                              void* d_out, int out_size) {
    const float* z  = (const float*)d_in[0];
    const float* cb = (const float*)d_in[1];
    if (n_in >= 2 && in_sizes[0] == CB_ELEMS && in_sizes[1] == ZQ_ELEMS) {
        const float* tmp = z; z = cb; cb = tmp;
    }
    float* out = (float*)d_out;

    static bool attr_set = false;
    if (!attr_set) {
        cudaFuncSetAttribute(vq_screen_kernel,
                             cudaFuncAttributeMaxDynamicSharedMemorySize,
                             SMEM_DYN);
        attr_set = true;
    }

    int nwarps = M_ROWS + K_CODES;
    vq_prep_kernel<<<(nwarps * 32 + 255) / 256, 256>>>(z, cb);

    dim3 sgrid(M_ROWS / GTM, NSPLIT);
    vq_screen_kernel<<<sgrid, 256, SMEM_DYN>>>();

    vq_rescore_kernel<<<(M_ROWS * 32 + 255) / 256, 256>>>(z, cb, out, out_size);
    vq_finalize_kernel<<<1, 1>>>(out, out_size);
}